// round 9
// baseline (speedup 1.0000x reference)
#include <cuda_runtime.h>
#include <cuda_bf16.h>
#include <cstdint>

// Sparse average pooling, output-driven two-phase (R3 structure, best measured):
//   Phase A: memset node zeroes per-output counters (replaces 4us kernel)
//   Phase B: invert rulebook into fixed-capacity buckets (4 rules/thread)
//   Phase C: per-output gather (16 threads/row, int4 bucket loads, __ldg
//            input loads) -> one coalesced streaming store.
// Lessons locked in: __ldg (not .cg) on input gathers; gather kernel is
// store-free except the output row; gather restructuring beyond R3 is neutral
// (DRAM random-access floored at ~5 TB/s).

#define CAP 32
#define NOUT_CAP 400000
#define NRULE_CAP 1600000

__device__ int g_counts[NOUT_CAP];
__device__ int g_bucket[(size_t)NOUT_CAP * CAP];

__global__ void bucket_scatter_kernel(const int* __restrict__ rules_in,
                                      const int* __restrict__ rules_out,
                                      int n_rules)
{
    int t = blockIdx.x * blockDim.x + threadIdx.x;
    int base = t * 4;
    if (base >= n_rules) return;

    if (base + 4 <= n_rules) {
        int4 ri = *reinterpret_cast<const int4*>(rules_in  + base);
        int4 ro = *reinterpret_cast<const int4*>(rules_out + base);
        int s;
        s = atomicAdd(&g_counts[ro.x], 1); if (s < CAP) g_bucket[(size_t)ro.x * CAP + s] = ri.x;
        s = atomicAdd(&g_counts[ro.y], 1); if (s < CAP) g_bucket[(size_t)ro.y * CAP + s] = ri.y;
        s = atomicAdd(&g_counts[ro.z], 1); if (s < CAP) g_bucket[(size_t)ro.z * CAP + s] = ri.z;
        s = atomicAdd(&g_counts[ro.w], 1); if (s < CAP) g_bucket[(size_t)ro.w * CAP + s] = ri.w;
    } else {
        for (int r = base; r < n_rules; r++) {
            int ro = rules_out[r];
            int s = atomicAdd(&g_counts[ro], 1);
            if (s < CAP) g_bucket[(size_t)ro * CAP + s] = rules_in[r];
        }
    }
}

__global__ void gather_kernel(const float* __restrict__ input,
                              float* __restrict__ out,
                              int n_out)
{
    const float scale = 0.125f;   // 1 / POOL_VOLUME

    long long gid = (long long)blockIdx.x * blockDim.x + threadIdx.x;
    int o = (int)(gid >> 4);      // output row
    int c = (int)(gid & 15);      // float4 chunk (0..15)
    if (o >= n_out) return;

    int n = g_counts[o];
    if (n > CAP) n = CAP;

    const int4* bk4 = reinterpret_cast<const int4*>(g_bucket + (size_t)o * CAP);
    const float4* in4 = reinterpret_cast<const float4*>(input);

    float4 acc = make_float4(0.f, 0.f, 0.f, 0.f);

    // 4 contributing rows per group: one 16B index load, 4 independent gathers.
    for (int base = 0; base < n; base += 4) {
        int4 idx = __ldcs(bk4 + (base >> 2));
        int m = n - base;

        float4 v0, v1, v2, v3;
        bool p1 = (m > 1), p2 = (m > 2), p3 = (m > 3);
        v0 = __ldg(in4 + (size_t)idx.x * 16 + c);
        if (p1) v1 = __ldg(in4 + (size_t)idx.y * 16 + c);
        if (p2) v2 = __ldg(in4 + (size_t)idx.z * 16 + c);
        if (p3) v3 = __ldg(in4 + (size_t)idx.w * 16 + c);

        acc.x += v0.x; acc.y += v0.y; acc.z += v0.z; acc.w += v0.w;
        if (p1) { acc.x += v1.x; acc.y += v1.y; acc.z += v1.z; acc.w += v1.w; }
        if (p2) { acc.x += v2.x; acc.y += v2.y; acc.z += v2.z; acc.w += v2.w; }
        if (p3) { acc.x += v3.x; acc.y += v3.y; acc.z += v3.z; acc.w += v3.w; }
    }
    acc.x *= scale; acc.y *= scale; acc.z *= scale; acc.w *= scale;

    __stcs(reinterpret_cast<float4*>(out + (size_t)o * 64) + c, acc);
}

// Fallback path (direct atomic scatter) if sizes exceed scratch capacity.
__global__ void avgpool_scatter_kernel(const float* __restrict__ input,
                                       const int* __restrict__ rules_in,
                                       const int* __restrict__ rules_out,
                                       float* __restrict__ out,
                                       int n_rules)
{
    const float scale = 0.125f;
    long long gid = (long long)blockIdx.x * blockDim.x + threadIdx.x;
    long long total = (long long)n_rules * 16;
    if (gid >= total) return;
    int r = (int)(gid >> 4);
    int c = (int)(gid & 15);
    int rin = rules_in[r];
    int rout = rules_out[r];
    const float4* src = reinterpret_cast<const float4*>(input + (long long)rin * 64) + c;
    float4 v = *src;
    v.x *= scale; v.y *= scale; v.z *= scale; v.w *= scale;
    float* dst = out + (long long)rout * 64 + c * 4;
    asm volatile("red.global.add.v4.f32 [%0], {%1, %2, %3, %4};"
                 :: "l"(dst), "f"(v.x), "f"(v.y), "f"(v.z), "f"(v.w) : "memory");
}

extern "C" void kernel_launch(void* const* d_in, const int* in_sizes, int n_in,
                              void* d_out, int out_size)
{
    const float* input     = (const float*)d_in[0];
    const int*   rules_in  = (const int*)d_in[1];
    const int*   rules_out = (const int*)d_in[2];
    float* out = (float*)d_out;

    int n_rules = in_sizes[1];
    int n_out   = out_size / 64;

    if (n_out > NOUT_CAP || n_rules > NRULE_CAP) {
        cudaMemsetAsync(out, 0, (size_t)out_size * sizeof(float));
        long long total = (long long)n_rules * 16;
        int threads = 256;
        long long blocks = (total + threads - 1) / threads;
        avgpool_scatter_kernel<<<(unsigned)blocks, threads>>>(
            input, rules_in, rules_out, out, n_rules);
        return;
    }

    // Phase A: zero counters via a memset node (cheaper than a kernel wave).
    // cudaGetSymbolAddress is a host-side query — capture-safe, no allocation.
    {
        void* counts_ptr = nullptr;
        cudaGetSymbolAddress(&counts_ptr, g_counts);
        cudaMemsetAsync(counts_ptr, 0, (size_t)n_out * sizeof(int));
    }

    // Phase B: invert rulebook (4 rules per thread)
    {
        int n_t = (n_rules + 3) / 4;
        int threads = 256;
        int blocks = (n_t + threads - 1) / threads;
        bucket_scatter_kernel<<<blocks, threads>>>(rules_in, rules_out, n_rules);
    }

    // Phase C: output-driven gather (16 threads/row)
    {
        long long total = (long long)n_out * 16;
        int threads = 256;
        long long blocks = (total + threads - 1) / threads;
        gather_kernel<<<(unsigned)blocks, threads>>>(input, out, n_out);
    }
}

// round 14
// speedup vs baseline: 1.0494x; 1.0494x over previous
#include <cuda_runtime.h>
#include <cuda_bf16.h>
#include <cstdint>

// Sparse average pooling, output-driven two-phase:
//   Phase A: memset node zeroes per-output counters
//   Phase B: invert rulebook into fixed-capacity buckets (4 rules/thread)
//   Phase C: per-output gather (16 threads/row, int4 bucket loads, __ldg)
// R10: CAP=24 (bucket 48MB->36MB, better L2 residency; overflow P ~ 5e-7
// across the whole problem, guard retained) and 128-thread gather blocks
// (halve block-tail imbalance from Poisson(4) row counts).

#define CAP 24                     // 96B per row, 16B-aligned
#define NOUT_CAP 400000
#define NRULE_CAP 1600000

__device__ int g_counts[NOUT_CAP];
__device__ int g_bucket[(size_t)NOUT_CAP * CAP];

__global__ void bucket_scatter_kernel(const int* __restrict__ rules_in,
                                      const int* __restrict__ rules_out,
                                      int n_rules)
{
    int t = blockIdx.x * blockDim.x + threadIdx.x;
    int base = t * 4;
    if (base >= n_rules) return;

    if (base + 4 <= n_rules) {
        int4 ri = *reinterpret_cast<const int4*>(rules_in  + base);
        int4 ro = *reinterpret_cast<const int4*>(rules_out + base);
        int s;
        s = atomicAdd(&g_counts[ro.x], 1); if (s < CAP) g_bucket[(size_t)ro.x * CAP + s] = ri.x;
        s = atomicAdd(&g_counts[ro.y], 1); if (s < CAP) g_bucket[(size_t)ro.y * CAP + s] = ri.y;
        s = atomicAdd(&g_counts[ro.z], 1); if (s < CAP) g_bucket[(size_t)ro.z * CAP + s] = ri.z;
        s = atomicAdd(&g_counts[ro.w], 1); if (s < CAP) g_bucket[(size_t)ro.w * CAP + s] = ri.w;
    } else {
        for (int r = base; r < n_rules; r++) {
            int ro = rules_out[r];
            int s = atomicAdd(&g_counts[ro], 1);
            if (s < CAP) g_bucket[(size_t)ro * CAP + s] = rules_in[r];
        }
    }
}

__global__ void __launch_bounds__(128)
gather_kernel(const float* __restrict__ input,
              float* __restrict__ out,
              int n_out)
{
    const float scale = 0.125f;   // 1 / POOL_VOLUME

    long long gid = (long long)blockIdx.x * blockDim.x + threadIdx.x;
    int o = (int)(gid >> 4);      // output row
    int c = (int)(gid & 15);      // float4 chunk (0..15)
    if (o >= n_out) return;

    int n = g_counts[o];
    if (n > CAP) n = CAP;

    const int4* bk4 = reinterpret_cast<const int4*>(g_bucket + (size_t)o * CAP);
    const float4* in4 = reinterpret_cast<const float4*>(input);

    float4 acc = make_float4(0.f, 0.f, 0.f, 0.f);

    // 4 contributing rows per group: one 16B index load, 4 independent gathers.
    for (int base = 0; base < n; base += 4) {
        int4 idx = __ldcs(bk4 + (base >> 2));
        int m = n - base;

        float4 v0, v1, v2, v3;
        bool p1 = (m > 1), p2 = (m > 2), p3 = (m > 3);
        v0 = __ldg(in4 + (size_t)idx.x * 16 + c);
        if (p1) v1 = __ldg(in4 + (size_t)idx.y * 16 + c);
        if (p2) v2 = __ldg(in4 + (size_t)idx.z * 16 + c);
        if (p3) v3 = __ldg(in4 + (size_t)idx.w * 16 + c);

        acc.x += v0.x; acc.y += v0.y; acc.z += v0.z; acc.w += v0.w;
        if (p1) { acc.x += v1.x; acc.y += v1.y; acc.z += v1.z; acc.w += v1.w; }
        if (p2) { acc.x += v2.x; acc.y += v2.y; acc.z += v2.z; acc.w += v2.w; }
        if (p3) { acc.x += v3.x; acc.y += v3.y; acc.z += v3.z; acc.w += v3.w; }
    }
    acc.x *= scale; acc.y *= scale; acc.z *= scale; acc.w *= scale;

    __stcs(reinterpret_cast<float4*>(out + (size_t)o * 64) + c, acc);
}

// Fallback path (direct atomic scatter) if sizes exceed scratch capacity.
__global__ void avgpool_scatter_kernel(const float* __restrict__ input,
                                       const int* __restrict__ rules_in,
                                       const int* __restrict__ rules_out,
                                       float* __restrict__ out,
                                       int n_rules)
{
    const float scale = 0.125f;
    long long gid = (long long)blockIdx.x * blockDim.x + threadIdx.x;
    long long total = (long long)n_rules * 16;
    if (gid >= total) return;
    int r = (int)(gid >> 4);
    int c = (int)(gid & 15);
    int rin = rules_in[r];
    int rout = rules_out[r];
    const float4* src = reinterpret_cast<const float4*>(input + (long long)rin * 64) + c;
    float4 v = *src;
    v.x *= scale; v.y *= scale; v.z *= scale; v.w *= scale;
    float* dst = out + (long long)rout * 64 + c * 4;
    asm volatile("red.global.add.v4.f32 [%0], {%1, %2, %3, %4};"
                 :: "l"(dst), "f"(v.x), "f"(v.y), "f"(v.z), "f"(v.w) : "memory");
}

extern "C" void kernel_launch(void* const* d_in, const int* in_sizes, int n_in,
                              void* d_out, int out_size)
{
    const float* input     = (const float*)d_in[0];
    const int*   rules_in  = (const int*)d_in[1];
    const int*   rules_out = (const int*)d_in[2];
    float* out = (float*)d_out;

    int n_rules = in_sizes[1];
    int n_out   = out_size / 64;

    if (n_out > NOUT_CAP || n_rules > NRULE_CAP) {
        cudaMemsetAsync(out, 0, (size_t)out_size * sizeof(float));
        long long total = (long long)n_rules * 16;
        int threads = 256;
        long long blocks = (total + threads - 1) / threads;
        avgpool_scatter_kernel<<<(unsigned)blocks, threads>>>(
            input, rules_in, rules_out, out, n_rules);
        return;
    }

    // Phase A: zero counters via a memset node.
    {
        void* counts_ptr = nullptr;
        cudaGetSymbolAddress(&counts_ptr, g_counts);
        cudaMemsetAsync(counts_ptr, 0, (size_t)n_out * sizeof(int));
    }

    // Phase B: invert rulebook (4 rules per thread)
    {
        int n_t = (n_rules + 3) / 4;
        int threads = 256;
        int blocks = (n_t + threads - 1) / threads;
        bucket_scatter_kernel<<<blocks, threads>>>(rules_in, rules_out, n_rules);
    }

    // Phase C: output-driven gather (16 threads/row, 128-thread blocks)
    {
        long long total = (long long)n_out * 16;
        int threads = 128;
        long long blocks = (total + threads - 1) / threads;
        gather_kernel<<<(unsigned)blocks, threads>>>(input, out, n_out);
    }
}